// round 15
// baseline (speedup 1.0000x reference)
#include <cuda_runtime.h>

// Spalize via memset + scatter: out is 98% zeros (each pixel is nonzero in
// exactly 1 of 50 k-planes).
//   1. cudaMemsetAsync zeros the whole output via the COPY ENGINE (graph
//      memset node) - tests whether the CE write path beats the measured
//      5.94 TB/s SM-store ceiling.
//   2. A small scatter kernel writes each pixel's 3 channel values into its
//      matching k-plane (3.1MB payload) and the mask tail.

#define KCH 50
#define CCH 3

__device__ __forceinline__ int detect_is64(const int* __restrict__ mask) {
    const int lane = threadIdx.x & 31;
    const int w1 = __ldg(&mask[2 * lane + 1]);
    const int w2 = __ldg(&mask[2 * (lane + 32) + 1]);
    const unsigned b = __ballot_sync(0xffffffffu, (w1 | w2) == 0);
    return b == 0xffffffffu;
}

// One thread per pixel: scatter img channels into the mask-selected k-plane,
// then the tail blocks write the mask itself as float.
__global__ void __launch_bounds__(256) spalize_scatter_kernel(
    const float* __restrict__ img,
    const int*   __restrict__ mask,
    float*       __restrict__ out,
    int HW,
    int nPixBlocks)    // blocks handling the scatter; rest do the tail
{
    const int is64 = detect_is64(mask);

    if (blockIdx.x >= nPixBlocks) {
        // ---- mask tail: out[n_img + i] = (float)mask[i], 4 per thread ----
        const int tb = blockIdx.x - nPixBlocks;
        const int q  = tb * blockDim.x + threadIdx.x;   // quad index
        const int nq = HW >> 2;
        if (q < nq) {
            int m0, m1, m2, m3;
            if (is64) {
                const int base = q * 8;
                m0 = mask[base + 0]; m1 = mask[base + 2];
                m2 = mask[base + 4]; m3 = mask[base + 6];
            } else {
                const int4 mm = reinterpret_cast<const int4*>(mask)[q];
                m0 = mm.x; m1 = mm.y; m2 = mm.z; m3 = mm.w;
            }
            float4 v = make_float4((float)m0, (float)m1, (float)m2, (float)m3);
            const long long n_img4 = (long long)KCH * CCH * (long long)(HW >> 2);
            __stcs(&reinterpret_cast<float4*>(out)[n_img4 + q], v);
        }
        return;
    }

    const int i = blockIdx.x * blockDim.x + threadIdx.x;  // pixel index
    if (i >= HW) return;

    const int m = is64 ? mask[2 * i] : mask[i];

    const float v0 = img[0 * HW + i];
    const float v1 = img[1 * HW + i];
    const float v2 = img[2 * HW + i];

    float* dst = out + (long long)(m * CCH) * HW + i;
    __stcs(dst + 0LL * HW, v0);
    __stcs(dst + 1LL * HW, v1);
    __stcs(dst + 2LL * HW, v2);
}

extern "C" void kernel_launch(void* const* d_in, const int* in_sizes, int n_in,
                              void* d_out, int out_size)
{
    const float* img  = (const float*)d_in[0];
    const int*   mask = (const int*)d_in[1];
    float*       out  = (float*)d_out;

    const int HW = in_sizes[0] / CCH;       // 512*512

    // 1. CE memset: zero the spalized region (157MB). Tail is fully
    //    overwritten by the kernel, but zeroing everything is harmless
    //    and keeps one contiguous memset node.
    const long long n_img = (long long)KCH * CCH * HW;
    cudaMemsetAsync(out, 0, (size_t)n_img * sizeof(float), 0);

    // 2. Scatter kernel (ordered after memset in-stream).
    const int threads    = 256;
    const int nPixBlocks = (HW + threads - 1) / threads;    // 1024
    const int nq         = HW >> 2;
    const bool wantTail  = ((long long)out_size >= n_img + HW);
    const int tailBlocks = wantTail ? (nq + threads - 1) / threads : 0;  // 256

    spalize_scatter_kernel<<<nPixBlocks + tailBlocks, threads>>>(
        img, mask, out, HW, nPixBlocks);
}

// round 16
// speedup vs baseline: 1.5540x; 1.5540x over previous
#include <cuda_runtime.h>

// Spalize: out[k][c][h][w] = img[c][h][w] * (mask[h][w] == k), k in [0,50),
// plus the mask appended (as float) if out_size covers it.
//
// FINAL. Single fused kernel at the HBM3e write-stream roofline:
// 161MB of .cs-streamed, fully-coalesced float4 stores at ~6.3 TB/s
// effective in-window (~= copy-engine memset rate, measured R15 -> both
// write engines share the same DRAM ceiling). Verified invariant to
// occupancy (42-83%), grid (1408-6656), store width (128/256b), all L2
// retention policies, and beats memset+scatter via CE.
//
// 1 quad/thread, KSPLIT=25 (KCHUNK=2), 6656 blocks, 256 threads.
// Mask dtype (int32 vs int64 jax demotion) detected inline per-warp via
// ballot over the first 64 odd 32-bit words (all-zero <=> little-endian
// int64 in [0,50); false-positive prob ~50^-64).

#define KCH 50
#define CCH 3
#define KSPLIT 25
#define KCHUNK (KCH / KSPLIT)   // 2

__device__ __forceinline__ int detect_is64(const int* __restrict__ mask) {
    const int lane = threadIdx.x & 31;
    const int w1 = __ldg(&mask[2 * lane + 1]);
    const int w2 = __ldg(&mask[2 * (lane + 32) + 1]);
    const unsigned b = __ballot_sync(0xffffffffu, (w1 | w2) == 0);
    return b == 0xffffffffu;
}

__device__ __forceinline__ void load_mask_quad(const int* __restrict__ mask,
                                               int q, int is64,
                                               int& m0, int& m1, int& m2, int& m3) {
    if (is64) {
        const int base = q * 8;   // 4 int64s; low word at even idx
        m0 = mask[base + 0]; m1 = mask[base + 2];
        m2 = mask[base + 4]; m3 = mask[base + 6];
    } else {
        const int4 mm = reinterpret_cast<const int4*>(mask)[q];
        m0 = mm.x; m1 = mm.y; m2 = mm.z; m3 = mm.w;
    }
}

__device__ __forceinline__ float4 sel4(float4 ic, int m0, int m1, int m2, int m3, int k) {
    float4 v;
    v.x = (m0 == k) ? ic.x : 0.0f;
    v.y = (m1 == k) ? ic.y : 0.0f;
    v.z = (m2 == k) ? ic.z : 0.0f;
    v.w = (m3 == k) ? ic.w : 0.0f;
    return v;
}

__global__ void __launch_bounds__(256) spalize_fused_kernel(
    const float* __restrict__ img,
    const int*   __restrict__ mask,
    float*       __restrict__ out,
    int nq,            // HW/4
    int nblocksQ,      // ceil(nq/256)
    int nSpalBlocks)   // nblocksQ * KSPLIT
{
    const int is64 = detect_is64(mask);

    if (blockIdx.x >= nSpalBlocks) {
        // ---- mask tail: out[n_img + i] = (float)mask[i], 4 per thread ----
        const int tb = blockIdx.x - nSpalBlocks;
        const int q  = tb * blockDim.x + threadIdx.x;
        if (q < nq) {
            int m0, m1, m2, m3;
            load_mask_quad(mask, q, is64, m0, m1, m2, m3);
            float4 v = make_float4((float)m0, (float)m1, (float)m2, (float)m3);
            const long long n_img4 = (long long)KCH * CCH * nq;  // float4 units
            __stcs(&reinterpret_cast<float4*>(out)[n_img4 + q], v);
        }
        return;
    }

    // ---- spalize: 1 quad per thread, lanes contiguous ----
    const int qb = blockIdx.x % nblocksQ;
    const int ks = blockIdx.x / nblocksQ;
    const int q  = qb * blockDim.x + threadIdx.x;
    if (q >= nq) return;

    int m0, m1, m2, m3;
    load_mask_quad(mask, q, is64, m0, m1, m2, m3);

    const float4* img4 = reinterpret_cast<const float4*>(img);
    float4 ic0 = img4[0 * nq + q];
    float4 ic1 = img4[1 * nq + q];
    float4 ic2 = img4[2 * nq + q];

    float4* out4 = reinterpret_cast<float4*>(out);
    const int k0 = ks * KCHUNK;

    #pragma unroll
    for (int kk = 0; kk < KCHUNK; kk++) {
        const int k = k0 + kk;
        const long long obase = (long long)(k * CCH) * nq + q;
        __stcs(&out4[obase + 0LL * nq], sel4(ic0, m0, m1, m2, m3, k));
        __stcs(&out4[obase + 1LL * nq], sel4(ic1, m0, m1, m2, m3, k));
        __stcs(&out4[obase + 2LL * nq], sel4(ic2, m0, m1, m2, m3, k));
    }
}

extern "C" void kernel_launch(void* const* d_in, const int* in_sizes, int n_in,
                              void* d_out, int out_size)
{
    const float* img  = (const float*)d_in[0];
    const int*   mask = (const int*)d_in[1];
    float*       out  = (float*)d_out;

    const int HW = in_sizes[0] / CCH;       // 512*512
    const int nq = HW >> 2;                 // 65536

    const int threads     = 256;
    const int nblocksQ    = (nq + threads - 1) / threads;   // 256
    const int nSpalBlocks = nblocksQ * KSPLIT;              // 6400

    const long long n_img = (long long)KCH * CCH * HW;
    const bool wantTail = ((long long)out_size >= n_img + HW);
    const int grid = nSpalBlocks + (wantTail ? nblocksQ : 0);

    spalize_fused_kernel<<<grid, threads>>>(img, mask, out, nq, nblocksQ, nSpalBlocks);
}